// round 3
// baseline (speedup 1.0000x reference)
#include <cuda_runtime.h>
#include <cstdint>

#define NV 1000000
#define KK 27
#define TV 1024
#define NT 977                 // ceil(NV/TV)
#define NSEG (NT*KK)           // 26379
#define THR 512
#define NW 16                  // warps per conv block
#define CNT_GRID 3907          // ceil(NV/256)

// ---------------- scratch (static device globals; no allocation) ----------------
__device__ float    g_t1[NV * 32];
__device__ float    g_t5[NV * 32];
__device__ float    g_a[NV * 8];
__device__ float    g_b[NV * 8];
__device__ unsigned g_ent2[NV * KK];   // per-(tile,k) segments: src(20b) | dl(10b)<<20
__device__ int      g_segcnt[NSEG];
__device__ int      g_segcur[NSEG];
__device__ int      g_segoff[NSEG + 1];
__device__ float    g_w1f[KK * 8 * 32];
__device__ int      g_maskmode;        // 0 = 1-byte mask elems, 1 = 4-byte

__device__ __forceinline__ bool mask_at(const unsigned char* m, size_t e, int mode) {
    if (mode == 0) return m[e] != 0;
    return ((const unsigned*)m)[e] != 0u;
}

// ---------------- prep kernel 0: detect mask dtype + fold Wd0 + zero seg arrays --
__global__ void prep_init(const unsigned char* __restrict__ m,
                          const float* __restrict__ Wd0) {
    int b = blockIdx.x;
    if (b == 0) {
        // dtype probe over first 1MB (plane k=0 has ~59k nonzero bytes if uint8)
        __shared__ int s_any;
        if (threadIdx.x == 0) s_any = 0;
        __syncthreads();
        int any = 0;
        for (int j = threadIdx.x; j < 1000000; j += blockDim.x)
            if ((j & 3) != 0 && m[j] != 0) any = 1;
        if (any) atomicOr(&s_any, 1);
        __syncthreads();
        if (threadIdx.x == 0) g_maskmode = s_any ? 0 : 1;
    } else if (b <= 27) {
        int i = (b - 1) * 256 + threadIdx.x;     // over 27*8*32 = 6912
        if (i < KK * 8 * 32) {
            int co = i & 31, c = (i >> 5) & 7, k = i >> 8;
            float s = 0.f;
#pragma unroll
            for (int j = 0; j < 4; j++) s += Wd0[k * 1024 + (8 * j + c) * 32 + co];
            g_w1f[k * 256 + c * 32 + co] = s;
        }
    } else {
        int i = (b - 28) * 256 + threadIdx.x;    // zero 2*NSEG ints
        if (i < NSEG) { g_segcnt[i] = 0; g_segcur[i] = 0; }
        else if (i < 2 * NSEG) { /* second half maps nothing extra */ }
        int j = i - NSEG;
        if (j >= 0 && j < NSEG) g_segcur[j] = 0;  // (redundant-safe)
    }
}

// ---------------- prep kernel 1: per-(tile,k) counts ----------------
__global__ void count_seg(const unsigned char* __restrict__ mask) {
    int n = blockIdx.x * 256 + threadIdx.x;
    if (n >= NV) return;
    int mode = g_maskmode;
    int tile = n >> 10;
#pragma unroll 1
    for (int k = 0; k < KK; k++)
        if (mask_at(mask, (size_t)k * NV + n, mode))
            atomicAdd(&g_segcnt[tile * KK + k], 1);
}

// ---------------- prep kernel 2: exclusive scan of 26379 counts (1 block) -------
__global__ void scan_seg() {
    __shared__ int s[1024];
    int t = threadIdx.x;
    int base = t * 26;
    int loc[26];
    int sum = 0;
#pragma unroll
    for (int i = 0; i < 26; i++) {
        int v = (base + i < NSEG) ? g_segcnt[base + i] : 0;
        loc[i] = sum; sum += v;
    }
    s[t] = sum;
    __syncthreads();
#pragma unroll
    for (int off = 1; off < 1024; off <<= 1) {
        int x = (t >= off) ? s[t - off] : 0;
        __syncthreads();
        s[t] += x;
        __syncthreads();
    }
    int excl = s[t] - sum;
#pragma unroll
    for (int i = 0; i < 26; i++)
        if (base + i < NSEG) g_segoff[base + i] = excl + loc[i];
    if (t == 1023) g_segoff[NSEG] = s[1023];
}

// ---------------- prep kernel 3: fill segments (atomic cursor; order-free) ------
// Entry order within a (tile,k) segment doesn't affect output bitwise: each dst
// is touched exactly once per segment, and k-rounds execute in fixed order.
__global__ void fill_seg(const unsigned char* __restrict__ mask,
                         const int* __restrict__ idx) {
    int n = blockIdx.x * 256 + threadIdx.x;
    if (n >= NV) return;
    int mode = g_maskmode;
    int tile = n >> 10;
    unsigned dl = (unsigned)(n & 1023) << 20;
#pragma unroll 1
    for (int k = 0; k < KK; k++) {
        size_t e = (size_t)k * NV + n;
        if (mask_at(mask, e, mode)) {
            int seg = tile * KK + k;
            int p = atomicAdd(&g_segcur[seg], 1);
            g_ent2[g_segoff[seg] + p] = (unsigned)idx[e] | dl;
        }
    }
}

// ================= conv kernels: dst-tile + k-rounds + reg weights ==============

// CIN=32, COUT=32. MODE 0: out=acc ; MODE 2: out = acc + xres[n*8 + (co&7)]
template <int MODE>
__global__ void __launch_bounds__(THR) conv32_32(const float* __restrict__ in,
        const float* __restrict__ W, const float* __restrict__ xres,
        float* __restrict__ out) {
    extern __shared__ float s_acc[];               // TV*32 floats = 128KB
    const int t = blockIdx.x;
    const int tid = threadIdx.x, lane = tid & 31, wid = tid >> 5;
    for (int i = tid; i < TV * 8; i += THR) ((float4*)s_acc)[i] = make_float4(0, 0, 0, 0);
    __syncthreads();
    const int segbase = t * KK;
    for (int k = 0; k < KK; k++) {
        float wreg[32];
        const float* wk = W + k * 1024 + lane;
#pragma unroll
        for (int ci = 0; ci < 32; ci++) wreg[ci] = __ldg(wk + ci * 32);
        const int lo = g_segoff[segbase + k], hi = g_segoff[segbase + k + 1];
        for (int b = lo + wid * 4; b < hi; b += NW * 4) {
            unsigned e0 = 0, e1 = 0, e2 = 0, e3 = 0;
            float x0 = 0.f, x1 = 0.f, x2 = 0.f, x3 = 0.f;
            int nv = hi - b;                       // >=1
            e0 = __ldg(&g_ent2[b]);
            if (nv > 1) e1 = __ldg(&g_ent2[b + 1]);
            if (nv > 2) e2 = __ldg(&g_ent2[b + 2]);
            if (nv > 3) e3 = __ldg(&g_ent2[b + 3]);
            x0 = __ldg(in + (size_t)(e0 & 0xFFFFFu) * 32 + lane);
            if (nv > 1) x1 = __ldg(in + (size_t)(e1 & 0xFFFFFu) * 32 + lane);
            if (nv > 2) x2 = __ldg(in + (size_t)(e2 & 0xFFFFFu) * 32 + lane);
            if (nv > 3) x3 = __ldg(in + (size_t)(e3 & 0xFFFFFu) * 32 + lane);
            float a0 = 0.f, a1 = 0.f, a2 = 0.f, a3 = 0.f;
#pragma unroll
            for (int ci = 0; ci < 32; ci++) {
                float w = wreg[ci];
                a0 = fmaf(__shfl_sync(0xffffffffu, x0, ci), w, a0);
                a1 = fmaf(__shfl_sync(0xffffffffu, x1, ci), w, a1);
                a2 = fmaf(__shfl_sync(0xffffffffu, x2, ci), w, a2);
                a3 = fmaf(__shfl_sync(0xffffffffu, x3, ci), w, a3);
            }
            s_acc[(e0 >> 20) * 32 + lane] += a0;
            if (nv > 1) s_acc[(e1 >> 20) * 32 + lane] += a1;
            if (nv > 2) s_acc[(e2 >> 20) * 32 + lane] += a2;
            if (nv > 3) s_acc[(e3 >> 20) * 32 + lane] += a3;
        }
        __syncthreads();
    }
    const int base = t * TV;
    const int nval = min(TV, NV - base);
    if (MODE == 0) {
        float4* o4 = (float4*)out + (size_t)base * 8;
        for (int i = tid; i < nval * 8; i += THR) o4[i] = ((float4*)s_acc)[i];
    } else {
        float4* o4 = (float4*)out + (size_t)base * 8;
        for (int i = tid; i < nval * 8; i += THR) {
            int j = i >> 3, q = i & 7;             // co = 4q
            float4 a = ((float4*)s_acc)[i];
            const float4 xr = *(const float4*)(xres + (size_t)(base + j) * 8 + ((q & 1) * 4));
            a.x += xr.x; a.y += xr.y; a.z += xr.z; a.w += xr.w;
            o4[i] = a;
        }
    }
}

// CIN=8, COUT=32, MODE 0 only. W layout k*256 + ci*32 + co.
__global__ void __launch_bounds__(THR) conv8_32(const float* __restrict__ in,
        const float* __restrict__ W, float* __restrict__ out) {
    extern __shared__ float s_acc[];               // TV*32
    const int t = blockIdx.x;
    const int tid = threadIdx.x, lane = tid & 31, wid = tid >> 5;
    for (int i = tid; i < TV * 8; i += THR) ((float4*)s_acc)[i] = make_float4(0, 0, 0, 0);
    __syncthreads();
    const int segbase = t * KK;
    for (int k = 0; k < KK; k++) {
        float wreg[8];
        const float* wk = W + k * 256 + lane;
#pragma unroll
        for (int ci = 0; ci < 8; ci++) wreg[ci] = __ldg(wk + ci * 32);
        const int lo = g_segoff[segbase + k], hi = g_segoff[segbase + k + 1];
        for (int b = lo + wid * 4; b < hi; b += NW * 4) {
            unsigned e0 = 0, e1 = 0, e2 = 0, e3 = 0;
            float x0 = 0.f, x1 = 0.f, x2 = 0.f, x3 = 0.f;
            int nv = hi - b;
            e0 = __ldg(&g_ent2[b]);
            if (nv > 1) e1 = __ldg(&g_ent2[b + 1]);
            if (nv > 2) e2 = __ldg(&g_ent2[b + 2]);
            if (nv > 3) e3 = __ldg(&g_ent2[b + 3]);
            x0 = __ldg(in + (size_t)(e0 & 0xFFFFFu) * 8 + (lane & 7));
            if (nv > 1) x1 = __ldg(in + (size_t)(e1 & 0xFFFFFu) * 8 + (lane & 7));
            if (nv > 2) x2 = __ldg(in + (size_t)(e2 & 0xFFFFFu) * 8 + (lane & 7));
            if (nv > 3) x3 = __ldg(in + (size_t)(e3 & 0xFFFFFu) * 8 + (lane & 7));
            float a0 = 0.f, a1 = 0.f, a2 = 0.f, a3 = 0.f;
#pragma unroll
            for (int ci = 0; ci < 8; ci++) {
                float w = wreg[ci];
                a0 = fmaf(__shfl_sync(0xffffffffu, x0, ci), w, a0);
                a1 = fmaf(__shfl_sync(0xffffffffu, x1, ci), w, a1);
                a2 = fmaf(__shfl_sync(0xffffffffu, x2, ci), w, a2);
                a3 = fmaf(__shfl_sync(0xffffffffu, x3, ci), w, a3);
            }
            s_acc[(e0 >> 20) * 32 + lane] += a0;
            if (nv > 1) s_acc[(e1 >> 20) * 32 + lane] += a1;
            if (nv > 2) s_acc[(e2 >> 20) * 32 + lane] += a2;
            if (nv > 3) s_acc[(e3 >> 20) * 32 + lane] += a3;
        }
        __syncthreads();
    }
    const int base = t * TV;
    const int nval = min(TV, NV - base);
    float4* o4 = (float4*)out + (size_t)base * 8;
    for (int i = tid; i < nval * 8; i += THR) o4[i] = ((float4*)s_acc)[i];
}

// CIN=32, COUT=8, MODE 0. W layout k*256 + ci*8 + co. 4 entries/warp via subgroups.
__global__ void __launch_bounds__(THR) conv32_8(const float* __restrict__ in,
        const float* __restrict__ W, float* __restrict__ out) {
    extern __shared__ float s_acc[];               // TV*8 floats = 32KB
    const int t = blockIdx.x;
    const int tid = threadIdx.x, lane = tid & 31, wid = tid >> 5;
    const int co = lane & 7, sub = lane >> 3, qb = lane & 24;
    for (int i = tid; i < TV * 2; i += THR) ((float4*)s_acc)[i] = make_float4(0, 0, 0, 0);
    __syncthreads();
    int sl[8];
#pragma unroll
    for (int q = 0; q < 8; q++) sl[q] = qb + q;
    const int segbase = t * KK;
    for (int k = 0; k < KK; k++) {
        float wreg[32];
        const float* wk = W + k * 256 + co;
#pragma unroll
        for (int ci = 0; ci < 32; ci++) wreg[ci] = __ldg(wk + ci * 8);
        const int lo = g_segoff[segbase + k], hi = g_segoff[segbase + k + 1];
        for (int b = lo + wid * 4; b < hi; b += NW * 4) {
            const bool act = (b + sub) < hi;
            unsigned e = act ? __ldg(&g_ent2[b + sub]) : 0u;
            float4 xq = make_float4(0.f, 0.f, 0.f, 0.f);
            if (act) xq = *(const float4*)(in + (size_t)(e & 0xFFFFFu) * 32 + co * 4);
            float xa[4] = {xq.x, xq.y, xq.z, xq.w};
            float a0 = 0.f, a1 = 0.f;
#pragma unroll
            for (int ci = 0; ci < 16; ci++)
                a0 = fmaf(__shfl_sync(0xffffffffu, xa[ci & 3], sl[ci >> 2]), wreg[ci], a0);
#pragma unroll
            for (int ci = 16; ci < 32; ci++)
                a1 = fmaf(__shfl_sync(0xffffffffu, xa[ci & 3], sl[ci >> 2]), wreg[ci], a1);
            if (act) s_acc[(e >> 20) * 8 + co] += a0 + a1;
        }
        __syncthreads();
    }
    const int base = t * TV;
    const int nval = min(TV, NV - base);
    float4* o4 = (float4*)out + (size_t)base * 2;
    for (int i = tid; i < nval * 2; i += THR) o4[i] = ((float4*)s_acc)[i];
}

// CIN=8, COUT=8. MODE 0: out=acc ; MODE 1: out = xres - acc. W: k*64 + ci*8 + co.
template <int MODE>
__global__ void __launch_bounds__(THR) conv8_8(const float* __restrict__ in,
        const float* __restrict__ W, const float* __restrict__ xres,
        float* __restrict__ out) {
    extern __shared__ float s_acc[];               // TV*8
    const int t = blockIdx.x;
    const int tid = threadIdx.x, lane = tid & 31, wid = tid >> 5;
    const int co = lane & 7, sub = lane >> 3, qb = lane & 24;
    for (int i = tid; i < TV * 2; i += THR) ((float4*)s_acc)[i] = make_float4(0, 0, 0, 0);
    __syncthreads();
    int sl[8];
#pragma unroll
    for (int q = 0; q < 8; q++) sl[q] = qb + q;
    const int segbase = t * KK;
    for (int k = 0; k < KK; k++) {
        float wreg[8];
        const float* wk = W + k * 64 + co;
#pragma unroll
        for (int ci = 0; ci < 8; ci++) wreg[ci] = __ldg(wk + ci * 8);
        const int lo = g_segoff[segbase + k], hi = g_segoff[segbase + k + 1];
        for (int b = lo + wid * 4; b < hi; b += NW * 4) {
            const bool act = (b + sub) < hi;
            unsigned e = act ? __ldg(&g_ent2[b + sub]) : 0u;
            float xv = act ? __ldg(in + (size_t)(e & 0xFFFFFu) * 8 + co) : 0.f;
            float a = 0.f;
#pragma unroll
            for (int ci = 0; ci < 8; ci++)
                a = fmaf(__shfl_sync(0xffffffffu, xv, sl[ci]), wreg[ci], a);
            if (act) s_acc[(e >> 20) * 8 + co] += a;
        }
        __syncthreads();
    }
    const int base = t * TV;
    const int nval = min(TV, NV - base);
    float4* o4 = (float4*)out + (size_t)base * 2;
    if (MODE == 0) {
        for (int i = tid; i < nval * 2; i += THR) o4[i] = ((float4*)s_acc)[i];
    } else {
        const float4* xr4 = (const float4*)xres + (size_t)base * 2;
        for (int i = tid; i < nval * 2; i += THR) {
            float4 a = ((float4*)s_acc)[i];
            float4 xr = xr4[i];
            o4[i] = make_float4(xr.x - a.x, xr.y - a.y, xr.z - a.z, xr.w - a.w);
        }
    }
}

// ---------------- launcher ----------------
extern "C" void kernel_launch(void* const* d_in, const int* in_sizes, int n_in,
                              void* d_out, int out_size) {
    const float*         x    = (const float*)d_in[0];
    const int*           nidx = (const int*)d_in[1];
    const unsigned char* nmsk = (const unsigned char*)d_in[2];
    const float* Wd0 = (const float*)d_in[3];
    const float* Wd1 = (const float*)d_in[4];
    const float* Wd2 = (const float*)d_in[5];
    const float* Wu0 = (const float*)d_in[6];
    const float* Wu1 = (const float*)d_in[7];
    const float* Wu2 = (const float*)d_in[8];
    float* outp = (float*)d_out;

    void *p_t1, *p_t5, *p_a, *p_b, *p_w1f;
    cudaGetSymbolAddress(&p_t1, g_t1);
    cudaGetSymbolAddress(&p_t5, g_t5);
    cudaGetSymbolAddress(&p_a, g_a);
    cudaGetSymbolAddress(&p_b, g_b);
    cudaGetSymbolAddress(&p_w1f, g_w1f);
    float* t1  = (float*)p_t1;
    float* t5  = (float*)p_t5;
    float* sa  = (float*)p_a;
    float* sb  = (float*)p_b;
    float* w1f = (float*)p_w1f;

    const int SM32 = TV * 32 * 4;   // 131072
    const int SM8  = TV * 8 * 4;    // 32768
    cudaFuncSetAttribute(conv32_32<0>, cudaFuncAttributeMaxDynamicSharedMemorySize, SM32);
    cudaFuncSetAttribute(conv32_32<2>, cudaFuncAttributeMaxDynamicSharedMemorySize, SM32);
    cudaFuncSetAttribute(conv8_32,     cudaFuncAttributeMaxDynamicSharedMemorySize, SM32);

    // prep: 4 launches (so ncu -s 5 lands on a conv kernel)
    int zb = (2 * NSEG + 255) / 256;          // blocks to zero segcnt+segcur
    prep_init<<<1 + 27 + zb, 256>>>(nmsk, Wd0);
    count_seg<<<CNT_GRID, 256>>>(nmsk);
    scan_seg<<<1, 1024>>>();
    fill_seg<<<CNT_GRID, 256>>>(nmsk, nidx);

    // conv chain
    conv8_32 <<<NT, THR, SM32>>>(x,  w1f, t1);          // conv1 (folded Wd0): x -> t1
    conv32_8 <<<NT, THR, SM8 >>>(t1, Wd1, sa);          // conv2: t1 -> sa
    conv8_8<1><<<NT, THR, SM8 >>>(sa, Wd2, x, sb);      // conv3: sb = x - conv(sa)
    conv8_8<0><<<NT, THR, SM8 >>>(sb, Wu0, nullptr, sa);// conv4: sb -> sa
    conv8_32 <<<NT, THR, SM32>>>(sa, Wu1, t5);          // conv5: sa -> t5
    conv32_32<2><<<NT, THR, SM32>>>(t5, Wu2, x, outp);  // conv6: out = tile(x)+conv(t5)
    (void)in_sizes; (void)n_in; (void)out_size;
}

// round 4
// speedup vs baseline: 1.2256x; 1.2256x over previous
#include <cuda_runtime.h>
#include <cstdint>

#define NV 1000000
#define KK 27
#define TV 1024
#define NT 977                 // ceil(NV/TV)
#define NSEG (NT*KK)           // 26379
#define THR 512
#define NW 16

// ---------------- scratch ----------------
__device__ float    g_t1[NV * 32];
__device__ float    g_t5[NV * 32];
__device__ float    g_a[NV * 8];
__device__ float    g_b[NV * 8];
__device__ unsigned g_ent2[NV * KK];   // src(20b) | dst_local(10b)<<20, per (tile,k)
__device__ int      g_segcnt[NSEG];
__device__ int      g_segoff[NSEG + 1];
__device__ float    g_w1f[KK * 8 * 32];

// ---------------- prep 1: per-(tile,k) counts, smem counters, inline dtype probe
__global__ __launch_bounds__(256) void count_tile(const unsigned char* __restrict__ m) {
    __shared__ int cnt[KK];
    __shared__ int s_mode;
    const int tid = threadIdx.x;
    if (tid < KK) cnt[tid] = 0;
    if (tid == 0) s_mode = 1;
    __syncthreads();
    // dtype probe on first 1KB: uint8 mask has ~60 trues there -> some nonzero
    // byte at offset%4!=0. int32/float32 masks put value bytes only at %4==0.
    {
        unsigned char b1 = m[4 * tid + 1], b2 = m[4 * tid + 2], b3 = m[4 * tid + 3];
        if (b1 | b2 | b3) s_mode = 0;
    }
    __syncthreads();
    const int mode = s_mode;
    const int n0 = blockIdx.x * TV + tid * 4;          // NV%4==0 -> clean guard
    const bool inb = n0 < NV;
    for (int k = 0; k < KK; k++) {
        int c = 0;
        if (inb) {
            if (mode == 0) {
                uchar4 v = *(const uchar4*)(m + (size_t)k * NV + n0);
                c = (v.x != 0) + (v.y != 0) + (v.z != 0) + (v.w != 0);
            } else {
                int4 v = *(const int4*)((const int*)m + (size_t)k * NV + n0);
                c = (v.x != 0) + (v.y != 0) + (v.z != 0) + (v.w != 0);
            }
        }
#pragma unroll
        for (int o = 16; o; o >>= 1) c += __shfl_down_sync(0xffffffffu, c, o);
        if ((tid & 31) == 0 && c) atomicAdd(&cnt[k], c);
    }
    __syncthreads();
    if (tid < KK) g_segcnt[blockIdx.x * KK + tid] = cnt[tid];
}

// ---------------- prep 2: exclusive scan of counts + fold Wd0 ----------------
__global__ void scan_fold(const float* __restrict__ Wd0) {
    __shared__ int s[1024];
    const int t = threadIdx.x;
    const int base = t * 26;
    int loc[26];
    int sum = 0;
#pragma unroll
    for (int i = 0; i < 26; i++) {
        int v = (base + i < NSEG) ? g_segcnt[base + i] : 0;
        loc[i] = sum; sum += v;
    }
    s[t] = sum;
    __syncthreads();
#pragma unroll
    for (int off = 1; off < 1024; off <<= 1) {
        int x = (t >= off) ? s[t - off] : 0;
        __syncthreads();
        s[t] += x;
        __syncthreads();
    }
    const int excl = s[t] - sum;
#pragma unroll
    for (int i = 0; i < 26; i++)
        if (base + i < NSEG) g_segoff[base + i] = excl + loc[i];
    if (t == 1023) g_segoff[NSEG] = s[1023];
    // fold Wd0 [27,32,32] over the channel tiling -> w1f [27,8,32]
    for (int i = t; i < KK * 8 * 32; i += 1024) {
        int co = i & 31, c = (i >> 5) & 7, k = i >> 8;
        float v = 0.f;
#pragma unroll
        for (int j = 0; j < 4; j++) v += Wd0[k * 1024 + (8 * j + c) * 32 + co];
        g_w1f[k * 256 + c * 32 + co] = v;
    }
}

// ---------------- prep 3: fill segments (smem cursors) ----------------
// Order within a segment is arbitrary; each dst appears once per (tile,k)
// segment and k-rounds run in fixed order, so the conv output is deterministic.
__global__ __launch_bounds__(256) void fill_tile(const unsigned char* __restrict__ m,
                                                 const int* __restrict__ idx) {
    __shared__ int cur[KK];
    __shared__ int off[KK];
    __shared__ int s_mode;
    const int tid = threadIdx.x;
    if (tid < KK) { cur[tid] = 0; off[tid] = g_segoff[blockIdx.x * KK + tid]; }
    if (tid == 0) s_mode = 1;
    __syncthreads();
    {
        unsigned char b1 = m[4 * tid + 1], b2 = m[4 * tid + 2], b3 = m[4 * tid + 3];
        if (b1 | b2 | b3) s_mode = 0;
    }
    __syncthreads();
    const int mode = s_mode;
    const int n0 = blockIdx.x * TV + tid * 4;
    if (n0 >= NV) return;   // no further barriers below
    const unsigned dl0 = (unsigned)(n0 & 1023) << 20;
    for (int k = 0; k < KK; k++) {
        int t0, t1, t2, t3;
        if (mode == 0) {
            uchar4 v = *(const uchar4*)(m + (size_t)k * NV + n0);
            t0 = v.x; t1 = v.y; t2 = v.z; t3 = v.w;
        } else {
            int4 v = *(const int4*)((const int*)m + (size_t)k * NV + n0);
            t0 = v.x; t1 = v.y; t2 = v.z; t3 = v.w;
        }
        const int* ip = idx + (size_t)k * NV + n0;
        if (t0) { int p = atomicAdd(&cur[k], 1); g_ent2[off[k] + p] = (unsigned)ip[0] | dl0; }
        if (t1) { int p = atomicAdd(&cur[k], 1); g_ent2[off[k] + p] = (unsigned)ip[1] | (dl0 + (1u << 20)); }
        if (t2) { int p = atomicAdd(&cur[k], 1); g_ent2[off[k] + p] = (unsigned)ip[2] | (dl0 + (2u << 20)); }
        if (t3) { int p = atomicAdd(&cur[k], 1); g_ent2[off[k] + p] = (unsigned)ip[3] | (dl0 + (3u << 20)); }
    }
}

// ================= conv kernels =================
// 32-out convs: lane owns 2 output channels (colo, colo+16); 16-lane slot per
// entry; one shfl.idx feeds both slots (per-lane src). 8 entries/warp/pass.

// CIN=8 -> COUT=32 (conv1 with folded Wd0, conv5). W: k*256 + ci*32 + co.
__global__ void __launch_bounds__(THR, 1) conv8_32(const float* __restrict__ in,
        const float* __restrict__ W, float* __restrict__ out) {
    extern __shared__ float s_acc[];               // TV*32 = 128KB
    const int t = blockIdx.x, tid = threadIdx.x, lane = tid & 31, wid = tid >> 5;
    const int colo = lane & 15, sbit = lane & 16, cl7 = lane & 7;
    for (int i = tid; i < TV * 8; i += THR) ((float4*)s_acc)[i] = make_float4(0, 0, 0, 0);
    __syncthreads();
    const int segbase = t * KK;
    for (int k = 0; k < KK; k++) {
        float wlo[8], whi[8];
        const float* wk = W + k * 256 + colo;
#pragma unroll
        for (int ci = 0; ci < 8; ci++) { wlo[ci] = __ldg(wk + ci * 32); whi[ci] = __ldg(wk + ci * 32 + 16); }
        const int lo = g_segoff[segbase + k], hi = g_segoff[segbase + k + 1];
        for (int b = lo + wid * 8; b < hi; b += NW * 8) {
            const int eb = b + (sbit >> 2);        // slot*4
            unsigned e[4]; float xv[4];
            float alo[4] = {0, 0, 0, 0}, ahi[4] = {0, 0, 0, 0};
#pragma unroll
            for (int j = 0; j < 4; j++) {
                bool act = (eb + j) < hi;
                e[j] = act ? __ldg(&g_ent2[eb + j]) : 0u;
                xv[j] = act ? __ldg(in + (size_t)(e[j] & 0xFFFFFu) * 8 + cl7) : 0.f;
            }
#pragma unroll
            for (int ci = 0; ci < 8; ci++) {
#pragma unroll
                for (int j = 0; j < 4; j++) {
                    float bv = __shfl_sync(0xffffffffu, xv[j], sbit | ci);
                    alo[j] = fmaf(bv, wlo[ci], alo[j]);
                    ahi[j] = fmaf(bv, whi[ci], ahi[j]);
                }
            }
#pragma unroll
            for (int j = 0; j < 4; j++) if ((eb + j) < hi) {
                int d = (int)(e[j] >> 20) * 32;
                s_acc[d + colo] += alo[j];
                s_acc[d + 16 + colo] += ahi[j];
            }
        }
        __syncthreads();
    }
    const int base = t * TV, nval = min(TV, NV - base);
    float4* o4 = (float4*)out + (size_t)base * 8;
    for (int i = tid; i < nval * 8; i += THR) o4[i] = ((float4*)s_acc)[i];
}

// CIN=32 -> COUT=32, fused final add: out = acc + xres[n*8 + (co&7)]  (conv6)
__global__ void __launch_bounds__(THR, 1) conv32_32f(const float* __restrict__ in,
        const float* __restrict__ W, const float* __restrict__ xres,
        float* __restrict__ out) {
    extern __shared__ float s_acc[];               // TV*32 = 128KB
    const int t = blockIdx.x, tid = threadIdx.x, lane = tid & 31, wid = tid >> 5;
    const int colo = lane & 15, sbit = lane & 16;
    for (int i = tid; i < TV * 8; i += THR) ((float4*)s_acc)[i] = make_float4(0, 0, 0, 0);
    __syncthreads();
    const int segbase = t * KK;
    for (int k = 0; k < KK; k++) {
        float wlo[32], whi[32];
        const float* wk = W + k * 1024 + colo;
#pragma unroll
        for (int ci = 0; ci < 32; ci++) { wlo[ci] = __ldg(wk + ci * 32); whi[ci] = __ldg(wk + ci * 32 + 16); }
        const int lo = g_segoff[segbase + k], hi = g_segoff[segbase + k + 1];
        for (int b = lo + wid * 8; b < hi; b += NW * 8) {
            const int eb = b + (sbit >> 2);
            unsigned e[4]; float xlo[4], xhi[4];
            float alo[4] = {0, 0, 0, 0}, ahi[4] = {0, 0, 0, 0};
#pragma unroll
            for (int j = 0; j < 4; j++) {
                bool act = (eb + j) < hi;
                e[j] = act ? __ldg(&g_ent2[eb + j]) : 0u;
                const float* xp = in + (size_t)(e[j] & 0xFFFFFu) * 32 + colo;
                xlo[j] = act ? __ldg(xp) : 0.f;
                xhi[j] = act ? __ldg(xp + 16) : 0.f;
            }
#pragma unroll
            for (int ci = 0; ci < 32; ci++) {
#pragma unroll
                for (int j = 0; j < 4; j++) {
                    float bv = (ci < 16) ? __shfl_sync(0xffffffffu, xlo[j], sbit | ci)
                                         : __shfl_sync(0xffffffffu, xhi[j], sbit | (ci - 16));
                    alo[j] = fmaf(bv, wlo[ci], alo[j]);
                    ahi[j] = fmaf(bv, whi[ci], ahi[j]);
                }
            }
#pragma unroll
            for (int j = 0; j < 4; j++) if ((eb + j) < hi) {
                int d = (int)(e[j] >> 20) * 32;
                s_acc[d + colo] += alo[j];
                s_acc[d + 16 + colo] += ahi[j];
            }
        }
        __syncthreads();
    }
    const int base = t * TV, nval = min(TV, NV - base);
    float4* o4 = (float4*)out + (size_t)base * 8;
    for (int i = tid; i < nval * 8; i += THR) {
        int j = i >> 3, q = i & 7;                 // co base = 4q
        float4 a = ((float4*)s_acc)[i];
        const float4 xr = *(const float4*)(xres + (size_t)(base + j) * 8 + ((q & 1) * 4));
        a.x += xr.x; a.y += xr.y; a.z += xr.z; a.w += xr.w;
        o4[i] = a;
    }
}

// CIN=32 -> COUT=8 (conv2). W: k*256 + ci*8 + co. 8-lane subgroup per entry,
// 8 entries/warp/pass (2 per subgroup).
__global__ void __launch_bounds__(THR, 1) conv32_8(const float* __restrict__ in,
        const float* __restrict__ W, float* __restrict__ out) {
    extern __shared__ float s_acc[];               // TV*8 = 32KB
    const int t = blockIdx.x, tid = threadIdx.x, lane = tid & 31, wid = tid >> 5;
    const int co = lane & 7, sub = lane >> 3, qb = lane & 24;
    for (int i = tid; i < TV * 2; i += THR) ((float4*)s_acc)[i] = make_float4(0, 0, 0, 0);
    __syncthreads();
    const int segbase = t * KK;
    for (int k = 0; k < KK; k++) {
        float wreg[32];
        const float* wk = W + k * 256 + co;
#pragma unroll
        for (int ci = 0; ci < 32; ci++) wreg[ci] = __ldg(wk + ci * 8);
        const int lo = g_segoff[segbase + k], hi = g_segoff[segbase + k + 1];
        for (int b = lo + wid * 8; b < hi; b += NW * 8) {
            const bool a0 = (b + sub) < hi, a1 = (b + 4 + sub) < hi;
            unsigned e0 = a0 ? __ldg(&g_ent2[b + sub]) : 0u;
            unsigned e1 = a1 ? __ldg(&g_ent2[b + 4 + sub]) : 0u;
            float4 q0 = make_float4(0, 0, 0, 0), q1 = make_float4(0, 0, 0, 0);
            if (a0) q0 = *(const float4*)(in + (size_t)(e0 & 0xFFFFFu) * 32 + co * 4);
            if (a1) q1 = *(const float4*)(in + (size_t)(e1 & 0xFFFFFu) * 32 + co * 4);
            float x0[4] = {q0.x, q0.y, q0.z, q0.w};
            float x1[4] = {q1.x, q1.y, q1.z, q1.w};
            float s0 = 0.f, s1 = 0.f;
#pragma unroll
            for (int ci = 0; ci < 32; ci++) {
                int src = qb + (ci >> 2);
                s0 = fmaf(__shfl_sync(0xffffffffu, x0[ci & 3], src), wreg[ci], s0);
                s1 = fmaf(__shfl_sync(0xffffffffu, x1[ci & 3], src), wreg[ci], s1);
            }
            if (a0) s_acc[(e0 >> 20) * 8 + co] += s0;
            if (a1) s_acc[(e1 >> 20) * 8 + co] += s1;
        }
        __syncthreads();
    }
    const int base = t * TV, nval = min(TV, NV - base);
    float4* o4 = (float4*)out + (size_t)base * 2;
    for (int i = tid; i < nval * 2; i += THR) o4[i] = ((float4*)s_acc)[i];
}

// CIN=8 -> COUT=8. MODE 0: out=acc ; MODE 1: out = xres - acc. W: k*64+ci*8+co.
template <int MODE>
__global__ void __launch_bounds__(THR, 1) conv8_8(const float* __restrict__ in,
        const float* __restrict__ W, const float* __restrict__ xres,
        float* __restrict__ out) {
    extern __shared__ float s_acc[];               // TV*8
    const int t = blockIdx.x, tid = threadIdx.x, lane = tid & 31, wid = tid >> 5;
    const int co = lane & 7, sub = lane >> 3, qb = lane & 24;
    for (int i = tid; i < TV * 2; i += THR) ((float4*)s_acc)[i] = make_float4(0, 0, 0, 0);
    __syncthreads();
    const int segbase = t * KK;
    for (int k = 0; k < KK; k++) {
        float wreg[8];
        const float* wk = W + k * 64 + co;
#pragma unroll
        for (int ci = 0; ci < 8; ci++) wreg[ci] = __ldg(wk + ci * 8);
        const int lo = g_segoff[segbase + k], hi = g_segoff[segbase + k + 1];
        for (int b = lo + wid * 8; b < hi; b += NW * 8) {
            const bool a0 = (b + sub) < hi, a1 = (b + 4 + sub) < hi;
            unsigned e0 = a0 ? __ldg(&g_ent2[b + sub]) : 0u;
            unsigned e1 = a1 ? __ldg(&g_ent2[b + 4 + sub]) : 0u;
            float x0 = a0 ? __ldg(in + (size_t)(e0 & 0xFFFFFu) * 8 + co) : 0.f;
            float x1 = a1 ? __ldg(in + (size_t)(e1 & 0xFFFFFu) * 8 + co) : 0.f;
            float s0 = 0.f, s1 = 0.f;
#pragma unroll
            for (int ci = 0; ci < 8; ci++) {
                s0 = fmaf(__shfl_sync(0xffffffffu, x0, qb + ci), wreg[ci], s0);
                s1 = fmaf(__shfl_sync(0xffffffffu, x1, qb + ci), wreg[ci], s1);
            }
            if (a0) s_acc[(e0 >> 20) * 8 + co] += s0;
            if (a1) s_acc[(e1 >> 20) * 8 + co] += s1;
        }
        __syncthreads();
    }
    const int base = t * TV, nval = min(TV, NV - base);
    float4* o4 = (float4*)out + (size_t)base * 2;
    if (MODE == 0) {
        for (int i = tid; i < nval * 2; i += THR) o4[i] = ((float4*)s_acc)[i];
    } else {
        const float4* xr4 = (const float4*)xres + (size_t)base * 2;
        for (int i = tid; i < nval * 2; i += THR) {
            float4 a = ((float4*)s_acc)[i];
            float4 xr = xr4[i];
            o4[i] = make_float4(xr.x - a.x, xr.y - a.y, xr.z - a.z, xr.w - a.w);
        }
    }
}

// ---------------- launcher ----------------
extern "C" void kernel_launch(void* const* d_in, const int* in_sizes, int n_in,
                              void* d_out, int out_size) {
    const float*         x    = (const float*)d_in[0];
    const int*           nidx = (const int*)d_in[1];
    const unsigned char* nmsk = (const unsigned char*)d_in[2];
    const float* Wd0 = (const float*)d_in[3];
    const float* Wd1 = (const float*)d_in[4];
    const float* Wd2 = (const float*)d_in[5];
    const float* Wu0 = (const float*)d_in[6];
    const float* Wu1 = (const float*)d_in[7];
    const float* Wu2 = (const float*)d_in[8];
    float* outp = (float*)d_out;

    void *p_t1, *p_t5, *p_a, *p_b, *p_w1f;
    cudaGetSymbolAddress(&p_t1, g_t1);
    cudaGetSymbolAddress(&p_t5, g_t5);
    cudaGetSymbolAddress(&p_a, g_a);
    cudaGetSymbolAddress(&p_b, g_b);
    cudaGetSymbolAddress(&p_w1f, g_w1f);
    float* t1  = (float*)p_t1;
    float* t5  = (float*)p_t5;
    float* sa  = (float*)p_a;
    float* sb  = (float*)p_b;
    float* w1f = (float*)p_w1f;

    const int SM32 = TV * 32 * 4;   // 131072
    const int SM8  = TV * 8 * 4;    // 32768
    cudaFuncSetAttribute(conv8_32,   cudaFuncAttributeMaxDynamicSharedMemorySize, SM32);
    cudaFuncSetAttribute(conv32_32f, cudaFuncAttributeMaxDynamicSharedMemorySize, SM32);

    // prep: exactly 3 launches so the first conv is launch #4 (ncu target)
    count_tile<<<NT, 256>>>(nmsk);
    scan_fold<<<1, 1024>>>(Wd0);
    fill_tile<<<NT, 256>>>(nmsk, nidx);

    // conv chain
    conv8_32 <<<NT, THR, SM32>>>(x,  w1f, t1);           // conv1 (folded Wd0)
    conv32_8 <<<NT, THR, SM8 >>>(t1, Wd1, sa);           // conv2
    conv8_8<1><<<NT, THR, SM8 >>>(sa, Wd2, x, sb);       // conv3: sb = x - conv(sa)
    conv8_8<0><<<NT, THR, SM8 >>>(sb, Wu0, nullptr, sa); // conv4
    conv8_32 <<<NT, THR, SM32>>>(sa, Wu1, t5);           // conv5
    conv32_32f<<<NT, THR, SM32>>>(t5, Wu2, x, outp);     // conv6: out = tile(x)+conv
    (void)in_sizes; (void)n_in; (void)out_size;
}

// round 5
// speedup vs baseline: 1.2515x; 1.0211x over previous
#include <cuda_runtime.h>
#include <cstdint>

#define NV 1000000
#define KK 27
#define TV 256
#define NT 3907                // ceil(NV/256)
#define NSEG (NT*KK)           // 105489
#define THR 192
#define NW 6
#define PB 977                 // prep blocks of 1024 voxels

// ---------------- scratch ----------------
__device__ float    g_t1[NV * 32];
__device__ float    g_t5[NV * 32];
__device__ float    g_a[NV * 8];
__device__ float    g_b[NV * 8];
__device__ unsigned g_ent2[NV * KK];   // src(20b) | dst_local(8b)<<20 per (tile256,k)
__device__ int      g_segcnt[NSEG];
__device__ int      g_segoff[NSEG + 1];
__device__ float    g_w1f[KK * 8 * 32];

// ---------------- prep 1: per-(tile256,k) counts ----------------
__global__ __launch_bounds__(256) void count_tile(const unsigned char* __restrict__ m) {
    __shared__ int cnt[108];
    __shared__ int s_mode;
    const int tid = threadIdx.x;
    if (tid < 108) cnt[tid] = 0;
    if (tid == 0) s_mode = 1;
    __syncthreads();
    {   // dtype probe: uint8 mask has nonzero bytes at off%4!=0 in first 1KB
        unsigned char b1 = m[4 * tid + 1], b2 = m[4 * tid + 2], b3 = m[4 * tid + 3];
        if (b1 | b2 | b3) s_mode = 0;
    }
    __syncthreads();
    const int mode = s_mode;
    const int n0 = blockIdx.x * 1024 + tid * 4;
    const bool inb = n0 < NV;
    const int st = tid >> 6;               // sub-tile 0..3 (constant per warp)
    for (int k = 0; k < KK; k++) {
        int c = 0;
        if (inb) {
            if (mode == 0) {
                uchar4 v = *(const uchar4*)(m + (size_t)k * NV + n0);
                c = (v.x != 0) + (v.y != 0) + (v.z != 0) + (v.w != 0);
            } else {
                int4 v = *(const int4*)((const int*)m + (size_t)k * NV + n0);
                c = (v.x != 0) + (v.y != 0) + (v.z != 0) + (v.w != 0);
            }
        }
#pragma unroll
        for (int o = 16; o; o >>= 1) c += __shfl_down_sync(0xffffffffu, c, o);
        if ((tid & 31) == 0 && c) atomicAdd(&cnt[st * 27 + k], c);
    }
    __syncthreads();
    if (tid < 108) {
        int seg = blockIdx.x * 108 + tid;
        if (seg < NSEG) g_segcnt[seg] = cnt[tid];
    }
}

// ---------------- prep 2: exclusive scan (chunked, no reg arrays) + fold Wd0 ----
__global__ void scan_fold(const float* __restrict__ Wd0) {
    __shared__ int s[1024];
    const int t = threadIdx.x;
    const int CH = (NSEG + 1023) / 1024;   // 104
    const int base = t * CH;
    const int end = min(base + CH, NSEG);
    int sum = 0;
    for (int i = base; i < end; i++) sum += g_segcnt[i];
    s[t] = sum;
    __syncthreads();
#pragma unroll
    for (int off = 1; off < 1024; off <<= 1) {
        int x = (t >= off) ? s[t - off] : 0;
        __syncthreads();
        s[t] += x;
        __syncthreads();
    }
    int run = s[t] - sum;
    for (int i = base; i < end; i++) { g_segoff[i] = run; run += g_segcnt[i]; }
    if (t == 1023) g_segoff[NSEG] = s[1023];
    // fold Wd0 [27,32,32] over channel tiling -> w1f [27,8,32]
    for (int i = t; i < KK * 8 * 32; i += 1024) {
        int co = i & 31, c = (i >> 5) & 7, k = i >> 8;
        float v = 0.f;
#pragma unroll
        for (int j = 0; j < 4; j++) v += Wd0[k * 1024 + (8 * j + c) * 32 + co];
        g_w1f[k * 256 + c * 32 + co] = v;
    }
}

// ---------------- prep 3: fill segments (smem cursors) ----------------
__global__ __launch_bounds__(256) void fill_tile(const unsigned char* __restrict__ m,
                                                 const int* __restrict__ idx) {
    __shared__ int cur[108];
    __shared__ int off[108];
    __shared__ int s_mode;
    const int tid = threadIdx.x;
    if (tid < 108) {
        cur[tid] = 0;
        int seg = blockIdx.x * 108 + tid;
        off[tid] = (seg < NSEG) ? g_segoff[seg] : 0;
    }
    if (tid == 0) s_mode = 1;
    __syncthreads();
    {
        unsigned char b1 = m[4 * tid + 1], b2 = m[4 * tid + 2], b3 = m[4 * tid + 3];
        if (b1 | b2 | b3) s_mode = 0;
    }
    __syncthreads();
    const int mode = s_mode;
    const int n0 = blockIdx.x * 1024 + tid * 4;
    if (n0 >= NV) return;
    const int st = tid >> 6;
    const unsigned dl0 = (unsigned)(n0 & 255) << 20;
    for (int k = 0; k < KK; k++) {
        int t0, t1, t2, t3;
        if (mode == 0) {
            uchar4 v = *(const uchar4*)(m + (size_t)k * NV + n0);
            t0 = v.x; t1 = v.y; t2 = v.z; t3 = v.w;
        } else {
            int4 v = *(const int4*)((const int*)m + (size_t)k * NV + n0);
            t0 = v.x; t1 = v.y; t2 = v.z; t3 = v.w;
        }
        const int* ip = idx + (size_t)k * NV + n0;
        const int c = st * 27 + k;
        if (t0) { int p = atomicAdd(&cur[c], 1); g_ent2[off[c] + p] = (unsigned)ip[0] | dl0; }
        if (t1) { int p = atomicAdd(&cur[c], 1); g_ent2[off[c] + p] = (unsigned)ip[1] | (dl0 + (1u << 20)); }
        if (t2) { int p = atomicAdd(&cur[c], 1); g_ent2[off[c] + p] = (unsigned)ip[2] | (dl0 + (2u << 20)); }
        if (t3) { int p = atomicAdd(&cur[c], 1); g_ent2[off[c] + p] = (unsigned)ip[3] | (dl0 + (3u << 20)); }
    }
}

// ================= conv kernels (TV=256, 32KB max static smem) =================

// CIN=8 -> COUT=32 (conv1 folded, conv5). No shuffles: each lane loads the full
// 8-float x row (2x LDG.128, L1 broadcast within 16-lane group). 2 ch/lane.
__global__ void __launch_bounds__(THR, 6) conv8_32(const float* __restrict__ in,
        const float* __restrict__ W, float* __restrict__ out) {
    __shared__ float s_acc[TV * 32];               // 32KB
    const int t = blockIdx.x, tid = threadIdx.x, lane = tid & 31, wid = tid >> 5;
    const int colo = lane & 15, sbit = lane & 16;
    for (int i = tid; i < TV * 8; i += THR) ((float4*)s_acc)[i] = make_float4(0, 0, 0, 0);
    __syncthreads();
    const int segbase = t * KK;
    for (int k = 0; k < KK; k++) {
        float wlo[8], whi[8];
        const float* wk = W + k * 256 + colo;
#pragma unroll
        for (int ci = 0; ci < 8; ci++) { wlo[ci] = __ldg(wk + ci * 32); whi[ci] = __ldg(wk + ci * 32 + 16); }
        const int lo = g_segoff[segbase + k], hi = g_segoff[segbase + k + 1];
        for (int b = lo + wid * 4; b < hi; b += NW * 4) {
            const int eb = b + (sbit >> 3);        // slot offset 0 or 2
#pragma unroll
            for (int j = 0; j < 2; j++) {
                const bool act = (eb + j) < hi;
                unsigned e = act ? __ldg(&g_ent2[eb + j]) : 0u;
                const float4* xp = (const float4*)(in + (size_t)(e & 0xFFFFFu) * 8);
                float4 x0 = act ? __ldg(xp) : make_float4(0, 0, 0, 0);
                float4 x1 = act ? __ldg(xp + 1) : make_float4(0, 0, 0, 0);
                float al = 0.f, ah = 0.f;
                al = fmaf(x0.x, wlo[0], al); ah = fmaf(x0.x, whi[0], ah);
                al = fmaf(x0.y, wlo[1], al); ah = fmaf(x0.y, whi[1], ah);
                al = fmaf(x0.z, wlo[2], al); ah = fmaf(x0.z, whi[2], ah);
                al = fmaf(x0.w, wlo[3], al); ah = fmaf(x0.w, whi[3], ah);
                al = fmaf(x1.x, wlo[4], al); ah = fmaf(x1.x, whi[4], ah);
                al = fmaf(x1.y, wlo[5], al); ah = fmaf(x1.y, whi[5], ah);
                al = fmaf(x1.z, wlo[6], al); ah = fmaf(x1.z, whi[6], ah);
                al = fmaf(x1.w, wlo[7], al); ah = fmaf(x1.w, whi[7], ah);
                if (act) {
                    int d = (int)(e >> 20) * 32;
                    s_acc[d + colo] += al;
                    s_acc[d + 16 + colo] += ah;
                }
            }
        }
        __syncthreads();
    }
    const int base = t * TV, nval = min(TV, NV - base);
    float4* o4 = (float4*)out + (size_t)base * 8;
    for (int i = tid; i < nval * 8; i += THR) o4[i] = ((float4*)s_acc)[i];
}

// CIN=32 -> COUT=32 + fused final add (conv6). ci-chunked (2x16) register weights.
__global__ void __launch_bounds__(THR, 6) conv32_32f(const float* __restrict__ in,
        const float* __restrict__ W, const float* __restrict__ xres,
        float* __restrict__ out) {
    __shared__ float s_acc[TV * 32];               // 32KB
    const int t = blockIdx.x, tid = threadIdx.x, lane = tid & 31, wid = tid >> 5;
    const int colo = lane & 15, sbit = lane & 16;
    for (int i = tid; i < TV * 8; i += THR) ((float4*)s_acc)[i] = make_float4(0, 0, 0, 0);
    __syncthreads();
    const int segbase = t * KK;
    for (int k = 0; k < KK; k++) {
        const int lo = g_segoff[segbase + k], hi = g_segoff[segbase + k + 1];
#pragma unroll 1
        for (int ch = 0; ch < 2; ch++) {
            float wlo[16], whi[16];
            const float* wk = W + k * 1024 + ch * 16 * 32 + colo;
#pragma unroll
            for (int ci = 0; ci < 16; ci++) { wlo[ci] = __ldg(wk + ci * 32); whi[ci] = __ldg(wk + ci * 32 + 16); }
            for (int b = lo + wid * 4; b < hi; b += NW * 4) {
                const int eb = b + (sbit >> 3);
#pragma unroll
                for (int j = 0; j < 2; j++) {
                    const bool act = (eb + j) < hi;
                    unsigned e = act ? __ldg(&g_ent2[eb + j]) : 0u;
                    float xv = act ? __ldg(in + (size_t)(e & 0xFFFFFu) * 32 + ch * 16 + colo) : 0.f;
                    float al = 0.f, ah = 0.f;
#pragma unroll
                    for (int ci = 0; ci < 16; ci++) {
                        float bv = __shfl_sync(0xffffffffu, xv, sbit | ci);
                        al = fmaf(bv, wlo[ci], al);
                        ah = fmaf(bv, whi[ci], ah);
                    }
                    if (act) {
                        int d = (int)(e >> 20) * 32;
                        s_acc[d + colo] += al;
                        s_acc[d + 16 + colo] += ah;
                    }
                }
            }
        }
        __syncthreads();
    }
    const int base = t * TV, nval = min(TV, NV - base);
    float4* o4 = (float4*)out + (size_t)base * 8;
    for (int i = tid; i < nval * 8; i += THR) {
        int j = i >> 3, q = i & 7;                 // co base = 4q
        float4 a = ((float4*)s_acc)[i];
        const float4 xr = *(const float4*)(xres + (size_t)(base + j) * 8 + ((q & 1) * 4));
        a.x += xr.x; a.y += xr.y; a.z += xr.z; a.w += xr.w;
        o4[i] = a;
    }
}

// CIN=32 -> COUT=8 (conv2). 8-lane subgroup per entry, float4 x + shfl.
__global__ void __launch_bounds__(THR, 5) conv32_8(const float* __restrict__ in,
        const float* __restrict__ W, float* __restrict__ out) {
    __shared__ float s_acc[TV * 8];                // 8KB
    const int t = blockIdx.x, tid = threadIdx.x, lane = tid & 31, wid = tid >> 5;
    const int co = lane & 7, sub = lane >> 3, qb = lane & 24;
    for (int i = tid; i < TV * 2; i += THR) ((float4*)s_acc)[i] = make_float4(0, 0, 0, 0);
    __syncthreads();
    const int segbase = t * KK;
    for (int k = 0; k < KK; k++) {
        float wreg[32];
        const float* wk = W + k * 256 + co;
#pragma unroll
        for (int ci = 0; ci < 32; ci++) wreg[ci] = __ldg(wk + ci * 8);
        const int lo = g_segoff[segbase + k], hi = g_segoff[segbase + k + 1];
        for (int b = lo + wid * 8; b < hi; b += NW * 8) {
            const bool a0 = (b + sub) < hi, a1 = (b + 4 + sub) < hi;
            unsigned e0 = a0 ? __ldg(&g_ent2[b + sub]) : 0u;
            unsigned e1 = a1 ? __ldg(&g_ent2[b + 4 + sub]) : 0u;
            float4 q0 = make_float4(0, 0, 0, 0), q1 = make_float4(0, 0, 0, 0);
            if (a0) q0 = __ldg((const float4*)(in + (size_t)(e0 & 0xFFFFFu) * 32 + co * 4));
            if (a1) q1 = __ldg((const float4*)(in + (size_t)(e1 & 0xFFFFFu) * 32 + co * 4));
            float x0[4] = {q0.x, q0.y, q0.z, q0.w};
            float x1[4] = {q1.x, q1.y, q1.z, q1.w};
            float s0 = 0.f, s1 = 0.f;
#pragma unroll
            for (int ci = 0; ci < 32; ci++) {
                int src = qb + (ci >> 2);
                s0 = fmaf(__shfl_sync(0xffffffffu, x0[ci & 3], src), wreg[ci], s0);
                s1 = fmaf(__shfl_sync(0xffffffffu, x1[ci & 3], src), wreg[ci], s1);
            }
            if (a0) s_acc[(e0 >> 20) * 8 + co] += s0;
            if (a1) s_acc[(e1 >> 20) * 8 + co] += s1;
        }
        __syncthreads();
    }
    const int base = t * TV, nval = min(TV, NV - base);
    float4* o4 = (float4*)out + (size_t)base * 2;
    for (int i = tid; i < nval * 2; i += THR) o4[i] = ((float4*)s_acc)[i];
}

// CIN=8 -> COUT=8 (conv3, conv4). No shuffles: lane loads full x row.
// MODE 0: out=acc ; MODE 1: out = xres - acc.
template <int MODE>
__global__ void __launch_bounds__(THR, 7) conv8_8(const float* __restrict__ in,
        const float* __restrict__ W, const float* __restrict__ xres,
        float* __restrict__ out) {
    __shared__ float s_acc[TV * 8];                // 8KB
    const int t = blockIdx.x, tid = threadIdx.x, lane = tid & 31, wid = tid >> 5;
    const int co = lane & 7, sub = lane >> 3;
    for (int i = tid; i < TV * 2; i += THR) ((float4*)s_acc)[i] = make_float4(0, 0, 0, 0);
    __syncthreads();
    const int segbase = t * KK;
    for (int k = 0; k < KK; k++) {
        float w[8];
        const float* wk = W + k * 64 + co;
#pragma unroll
        for (int ci = 0; ci < 8; ci++) w[ci] = __ldg(wk + ci * 8);
        const int lo = g_segoff[segbase + k], hi = g_segoff[segbase + k + 1];
        for (int b = lo + wid * 8; b < hi; b += NW * 8) {
            const int eb = b + sub * 2;
#pragma unroll
            for (int j = 0; j < 2; j++) {
                const bool act = (eb + j) < hi;
                unsigned e = act ? __ldg(&g_ent2[eb + j]) : 0u;
                const float4* xp = (const float4*)(in + (size_t)(e & 0xFFFFFu) * 8);
                float4 x0 = act ? __ldg(xp) : make_float4(0, 0, 0, 0);
                float4 x1 = act ? __ldg(xp + 1) : make_float4(0, 0, 0, 0);
                float a = 0.f;
                a = fmaf(x0.x, w[0], a); a = fmaf(x0.y, w[1], a);
                a = fmaf(x0.z, w[2], a); a = fmaf(x0.w, w[3], a);
                a = fmaf(x1.x, w[4], a); a = fmaf(x1.y, w[5], a);
                a = fmaf(x1.z, w[6], a); a = fmaf(x1.w, w[7], a);
                if (act) s_acc[(e >> 20) * 8 + co] += a;
            }
        }
        __syncthreads();
    }
    const int base = t * TV, nval = min(TV, NV - base);
    float4* o4 = (float4*)out + (size_t)base * 2;
    if (MODE == 0) {
        for (int i = tid; i < nval * 2; i += THR) o4[i] = ((float4*)s_acc)[i];
    } else {
        const float4* xr4 = (const float4*)xres + (size_t)base * 2;
        for (int i = tid; i < nval * 2; i += THR) {
            float4 a = ((float4*)s_acc)[i];
            float4 xr = xr4[i];
            o4[i] = make_float4(xr.x - a.x, xr.y - a.y, xr.z - a.z, xr.w - a.w);
        }
    }
}

// ---------------- launcher ----------------
extern "C" void kernel_launch(void* const* d_in, const int* in_sizes, int n_in,
                              void* d_out, int out_size) {
    const float*         x    = (const float*)d_in[0];
    const int*           nidx = (const int*)d_in[1];
    const unsigned char* nmsk = (const unsigned char*)d_in[2];
    const float* Wd0 = (const float*)d_in[3];
    const float* Wd1 = (const float*)d_in[4];
    const float* Wd2 = (const float*)d_in[5];
    const float* Wu0 = (const float*)d_in[6];
    const float* Wu1 = (const float*)d_in[7];
    const float* Wu2 = (const float*)d_in[8];
    float* outp = (float*)d_out;

    void *p_t1, *p_t5, *p_a, *p_b, *p_w1f;
    cudaGetSymbolAddress(&p_t1, g_t1);
    cudaGetSymbolAddress(&p_t5, g_t5);
    cudaGetSymbolAddress(&p_a, g_a);
    cudaGetSymbolAddress(&p_b, g_b);
    cudaGetSymbolAddress(&p_w1f, g_w1f);
    float* t1  = (float*)p_t1;
    float* t5  = (float*)p_t5;
    float* sa  = (float*)p_a;
    float* sb  = (float*)p_b;
    float* w1f = (float*)p_w1f;

    // prep: 3 launches so conv8_32 is launch #4 (ncu lands there)
    count_tile<<<PB, 256>>>(nmsk);
    scan_fold<<<1, 1024>>>(Wd0);
    fill_tile<<<PB, 256>>>(nmsk, nidx);

    // conv chain
    conv8_32 <<<NT, THR>>>(x,  w1f, t1);            // conv1 (folded Wd0)
    conv32_8 <<<NT, THR>>>(t1, Wd1, sa);            // conv2
    conv8_8<1><<<NT, THR>>>(sa, Wd2, x, sb);        // conv3: sb = x - conv(sa)
    conv8_8<0><<<NT, THR>>>(sb, Wu0, nullptr, sa);  // conv4
    conv8_32 <<<NT, THR>>>(sa, Wu1, t5);            // conv5
    conv32_32f<<<NT, THR>>>(t5, Wu2, x, outp);      // conv6: out = tile(x)+conv
    (void)in_sizes; (void)n_in; (void)out_size;
}

// round 7
// speedup vs baseline: 2.3755x; 1.8980x over previous
#include <cuda_runtime.h>
#include <cuda_bf16.h>
#include <cstdint>

#define NV 1000000
#define KK 27
#define MT 128
#define NTILE 7813              // ceil(NV/128)
#define NPAD (NTILE*128)        // 1000064
#define PB 977

// ---------------- scratch ----------------
__device__ uint4 g_xb[NV];           // x as bf16 [N,8]   (16B rows)
__device__ uint4 g_t1b[NV * 4];      // [N,32] bf16 (64B rows)
__device__ uint4 g_t5b[NV * 4];
__device__ uint4 g_sab[NV];          // [N,8] bf16
__device__ uint4 g_sbb[NV];
__device__ int   g_didx[NTILE * KK * 128];   // masked nbr idx or -1
__device__ __nv_bfloat16 g_wimg[71680];      // pre-swizzled B images (all 6 convs)
// wimg offsets (bf16): c1 0, c2 14336, c3 21504, c4 25088, c5 28672, c6 43008

// ---------------- helpers ----------------
__device__ __forceinline__ uint32_t smem_u32(const void* p) {
    uint32_t a;
    asm("{ .reg .u64 t; cvta.to.shared.u64 t, %1; cvt.u32.u64 %0, t; }" : "=r"(a) : "l"(p));
    return a;
}
static __device__ __forceinline__ uint32_t pkbf(float lo, float hi) {
    uint32_t r; asm("cvt.rn.bf16x2.f32 %0, %1, %2;" : "=r"(r) : "f"(hi), "f"(lo)); return r;
}
__device__ __forceinline__ uint32_t sw128(uint32_t b) { return b ^ ((b >> 3) & 0x70); }

__device__ __forceinline__ void ldsm4(uint32_t* r, uint32_t addr) {
    asm volatile("ldmatrix.sync.aligned.m8n8.x4.shared.b16 {%0,%1,%2,%3}, [%4];"
                 : "=r"(r[0]), "=r"(r[1]), "=r"(r[2]), "=r"(r[3]) : "r"(addr));
}
__device__ __forceinline__ void ldsm2(uint32_t* r, uint32_t addr) {
    asm volatile("ldmatrix.sync.aligned.m8n8.x2.shared.b16 {%0,%1}, [%2];"
                 : "=r"(r[0]), "=r"(r[1]) : "r"(addr));
}
__device__ __forceinline__ void mma16816(float* c, const uint32_t* a, const uint32_t* b) {
    asm volatile("mma.sync.aligned.m16n8k16.row.col.f32.bf16.bf16.f32 "
                 "{%0,%1,%2,%3}, {%4,%5,%6,%7}, {%8,%9}, {%0,%1,%2,%3};"
                 : "+f"(c[0]), "+f"(c[1]), "+f"(c[2]), "+f"(c[3])
                 : "r"(a[0]), "r"(a[1]), "r"(a[2]), "r"(a[3]), "r"(b[0]), "r"(b[1]));
}

// ---------------- prep 1: x -> bf16 ----------------
__global__ __launch_bounds__(256) void prep_x(const float* __restrict__ x) {
    const int n0 = blockIdx.x * 1024 + threadIdx.x * 4;
    if (n0 >= NV) return;
    const float4* xp = (const float4*)(x + (size_t)n0 * 8);
#pragma unroll
    for (int v = 0; v < 4; v++) {
        float4 a = xp[2 * v], b = xp[2 * v + 1];
        g_xb[n0 + v] = make_uint4(pkbf(a.x, a.y), pkbf(a.z, a.w),
                                  pkbf(b.x, b.y), pkbf(b.z, b.w));
    }
}

// ---------------- prep 2: weight images ([n][64k] rows, SW128, zero-padded) -----
__global__ __launch_bounds__(1024) void prep_wimg(const float* __restrict__ Wd0,
        const float* __restrict__ Wd1, const float* __restrict__ Wd2,
        const float* __restrict__ Wu0, const float* __restrict__ Wu1,
        const float* __restrict__ Wu2) {
    int e = blockIdx.x * 1024 + threadIdx.x;
    if (e >= 71680) return;
    int conv, off, N, TAPS, KPAD;
    if      (e < 14336) { conv = 0; off = 0;     N = 32; TAPS = 4; KPAD = 16; }
    else if (e < 21504) { conv = 1; off = 14336; N = 8;  TAPS = 2; KPAD = 32; }
    else if (e < 25088) { conv = 2; off = 21504; N = 8;  TAPS = 4; KPAD = 16; }
    else if (e < 28672) { conv = 3; off = 25088; N = 8;  TAPS = 4; KPAD = 16; }
    else if (e < 43008) { conv = 4; off = 28672; N = 32; TAPS = 4; KPAD = 16; }
    else                { conv = 5; off = 43008; N = 32; TAPS = 2; KPAD = 32; }
    int rem = e - off;
    int r = rem / (N * 64); rem -= r * N * 64;
    int n = rem >> 6;
    int j = rem & 63;
    int tp = j / KPAD, ci = j % KPAD;
    int k = r * TAPS + tp;
    float v = 0.f;
    if (k < KK) {
        if (conv == 0) { if (ci < 8) v = Wd0[k * 1024 + ci * 32 + n] + Wd0[k * 1024 + (8 + ci) * 32 + n]
                                       + Wd0[k * 1024 + (16 + ci) * 32 + n] + Wd0[k * 1024 + (24 + ci) * 32 + n]; }
        else if (conv == 1) { v = Wd1[k * 256 + ci * 8 + n]; }
        else if (conv == 2) { if (ci < 8) v = Wd2[k * 64 + ci * 8 + n]; }
        else if (conv == 3) { if (ci < 8) v = Wu0[k * 64 + ci * 8 + n]; }
        else if (conv == 4) { if (ci < 8) v = Wu1[k * 256 + ci * 32 + n]; }
        else                { v = Wu2[k * 1024 + ci * 32 + n]; }
    }
    uint32_t byte = (uint32_t)n * 128 + (uint32_t)j * 2;
    g_wimg[off + r * N * 64 + (sw128(byte) >> 1)] = __float2bfloat16(v);
}

// ---------------- prep 3: dense per-tile masked indices ----------------
__global__ __launch_bounds__(256) void prep_didx(const unsigned char* __restrict__ m,
                                                 const int* __restrict__ idx) {
    __shared__ int s_mode;
    const int tid = threadIdx.x;
    if (tid == 0) s_mode = 1;
    __syncthreads();
    { unsigned char b = m[4 * tid + 1] | m[4 * tid + 2] | m[4 * tid + 3]; if (b) s_mode = 0; }
    __syncthreads();
    const int mode = s_mode;
    const int n0 = blockIdx.x * 1024 + tid * 4;
    if (n0 >= NPAD) return;
    const int tile = n0 >> 7, dl0 = n0 & 127;
    int* dst = g_didx + (size_t)tile * KK * 128 + dl0;
    const bool inb = (n0 + 3) < NV;       // NV%4==0: chunk fully in or out
    for (int k = 0; k < KK; k++) {
        int4 o = make_int4(-1, -1, -1, -1);
        if (inb) {
            int t0, t1, t2, t3;
            if (mode == 0) {
                uchar4 v = *(const uchar4*)(m + (size_t)k * NV + n0);
                t0 = v.x; t1 = v.y; t2 = v.z; t3 = v.w;
            } else {
                int4 v = *(const int4*)((const int*)m + (size_t)k * NV + n0);
                t0 = v.x; t1 = v.y; t2 = v.z; t3 = v.w;
            }
            int4 iv = *(const int4*)(idx + (size_t)k * NV + n0);
            o.x = t0 ? iv.x : -1;
            o.y = t1 ? iv.y : -1;
            o.z = t2 ? iv.z : -1;
            o.w = t3 ? iv.w : -1;
        }
        *(int4*)(dst + k * 128) = o;
    }
}

// ---------------- tensor-core (mma.sync) sparse conv ----------------
// MODE 0: bf16 out = d ; MODE 1: bf16 out = x - d (NOUT=8) ; MODE 2: fp32 out = d + tile(x)
template <int CIN, int NOUT, int MODE>
__global__ __launch_bounds__(128) void conv_mma(const uint4* __restrict__ in,
        const uint4* __restrict__ wimg, const float* __restrict__ xres,
        void* __restrict__ outp) {
    constexpr int TAPS = (CIN == 8) ? 4 : 2;
    constexpr int R = (KK + TAPS - 1) / TAPS;   // 7 or 14
    constexpr int NTL = NOUT / 8;
    __shared__ __align__(1024) __nv_bfloat16 sA[MT * 64];    // 16KB
    __shared__ __align__(1024) __nv_bfloat16 sB[NOUT * 64];  // 4KB / 1KB
    const int tile = blockIdx.x, tid = threadIdx.x, lane = tid & 31, wid = tid >> 5;
    const uint32_t abase = smem_u32(sA), bbase = smem_u32(sB);
    const int* __restrict__ didx = g_didx + (size_t)tile * KK * 128;

    {   // zero A once (pad columns stay zero; real slots rewritten every round)
        uint4 z = make_uint4(0, 0, 0, 0);
        uint4* a4 = (uint4*)sA;
        for (int i = tid; i < MT * 8; i += 128) a4[i] = z;
    }
    float acc[2][NTL][4];
#pragma unroll
    for (int mt = 0; mt < 2; mt++)
#pragma unroll
        for (int nt = 0; nt < NTL; nt++)
#pragma unroll
            for (int q = 0; q < 4; q++) acc[mt][nt][q] = 0.f;
    __syncthreads();

    for (int r = 0; r < R; r++) {
        // copy this round's B image
        for (int i = tid; i < NOUT * 8; i += 128)
            ((uint4*)sB)[i] = __ldg(wimg + r * NOUT * 8 + i);
        // gather A (dense slots: value or zero)
        if (CIN == 8) {
#pragma unroll
            for (int s = tid; s < 512; s += 128) {
                const int tp = s >> 7, dl = s & 127, k = r * 4 + tp;
                if (k < KK) {
                    int v = didx[k * 128 + dl];
                    uint4 val = (v >= 0) ? __ldg(in + v) : make_uint4(0, 0, 0, 0);
                    *(uint4*)((char*)sA + sw128((uint32_t)dl * 128 + tp * 32)) = val;
                }
            }
        } else {
#pragma unroll
            for (int s = tid; s < 256; s += 128) {
                const int tp = s >> 7, dl = s & 127, k = r * 2 + tp;
                if (k < KK) {
                    int v = didx[k * 128 + dl];
                    if (v >= 0) {
                        const uint4* xp = in + (size_t)v * 4;
#pragma unroll
                        for (int q = 0; q < 4; q++)
                            *(uint4*)((char*)sA + sw128((uint32_t)dl * 128 + tp * 64 + q * 16)) = __ldg(xp + q);
                    } else {
                        uint4 z = make_uint4(0, 0, 0, 0);
#pragma unroll
                        for (int q = 0; q < 4; q++)
                            *(uint4*)((char*)sA + sw128((uint32_t)dl * 128 + tp * 64 + q * 16)) = z;
                    }
                }
            }
        }
        __syncthreads();
        // mma: K=64 in 4 k16 steps
        const int m0 = wid * 32;
#pragma unroll
        for (int ks = 0; ks < 4; ks++) {
            uint32_t a[2][4];
#pragma unroll
            for (int mt = 0; mt < 2; mt++) {
                uint32_t addr = abase + sw128((uint32_t)(m0 + mt * 16 + (lane & 15)) * 128
                                              + ks * 32 + ((lane >> 4) * 16));
                ldsm4(a[mt], addr);
            }
#pragma unroll
            for (int nt = 0; nt < NTL; nt++) {
                uint32_t b[2];
                uint32_t baddr = bbase + sw128((uint32_t)(nt * 8 + (lane & 7)) * 128
                                               + ks * 32 + (((lane >> 3) & 1) * 16));
                ldsm2(b, baddr);
                mma16816(acc[0][nt], a[0], b);
                mma16816(acc[1][nt], a[1], b);
            }
        }
        __syncthreads();
    }

    // epilogue from register fragments
    const int rbase = tile * 128 + wid * 32;
#pragma unroll
    for (int mt = 0; mt < 2; mt++) {
#pragma unroll
        for (int h = 0; h < 2; h++) {
            const int n = rbase + mt * 16 + (lane >> 2) + h * 8;
            if (n >= NV) continue;
            if (NOUT == 32) {
                if (MODE == 2) {
                    const float2 xr = *(const float2*)(xres + (size_t)n * 8 + (lane & 3) * 2);
                    float* o = (float*)outp + (size_t)n * 32 + (lane & 3) * 2;
#pragma unroll
                    for (int nt = 0; nt < NTL; nt++) {
                        float c0 = acc[mt][nt][h * 2], c1 = acc[mt][nt][h * 2 + 1];
                        *(float2*)(o + nt * 8) = make_float2(c0 + xr.x, c1 + xr.y);
                    }
                } else {
                    uint32_t* o = (uint32_t*)outp + (size_t)n * 16 + (lane & 3);
#pragma unroll
                    for (int nt = 0; nt < NTL; nt++)
                        o[nt * 4] = pkbf(acc[mt][nt][h * 2], acc[mt][nt][h * 2 + 1]);
                }
            } else {
                float c0 = acc[mt][0][h * 2], c1 = acc[mt][0][h * 2 + 1];
                if (MODE == 1) {
                    const float2 xr = *(const float2*)(xres + (size_t)n * 8 + (lane & 3) * 2);
                    c0 = xr.x - c0; c1 = xr.y - c1;
                }
                ((uint32_t*)outp)[(size_t)n * 4 + (lane & 3)] = pkbf(c0, c1);
            }
        }
    }
}

// ---------------- launcher ----------------
extern "C" void kernel_launch(void* const* d_in, const int* in_sizes, int n_in,
                              void* d_out, int out_size) {
    const float*         x    = (const float*)d_in[0];
    const int*           nidx = (const int*)d_in[1];
    const unsigned char* nmsk = (const unsigned char*)d_in[2];
    const float* Wd0 = (const float*)d_in[3];
    const float* Wd1 = (const float*)d_in[4];
    const float* Wd2 = (const float*)d_in[5];
    const float* Wu0 = (const float*)d_in[6];
    const float* Wu1 = (const float*)d_in[7];
    const float* Wu2 = (const float*)d_in[8];
    float* outp = (float*)d_out;

    void *p_xb, *p_t1, *p_t5, *p_sa, *p_sb, *p_w;
    cudaGetSymbolAddress(&p_xb, g_xb);
    cudaGetSymbolAddress(&p_t1, g_t1b);
    cudaGetSymbolAddress(&p_t5, g_t5b);
    cudaGetSymbolAddress(&p_sa, g_sab);
    cudaGetSymbolAddress(&p_sb, g_sbb);
    cudaGetSymbolAddress(&p_w,  g_wimg);
    const uint4* xb = (const uint4*)p_xb;
    uint4* t1b = (uint4*)p_t1;
    uint4* t5b = (uint4*)p_t5;
    uint4* sab = (uint4*)p_sa;
    uint4* sbb = (uint4*)p_sb;
    const uint4* wi = (const uint4*)p_w;   // bf16elems/8

    // prep: 3 launches -> conv1 is launch #4 (ncu target)
    prep_x   <<<PB, 256>>>(x);
    prep_wimg<<<70, 1024>>>(Wd0, Wd1, Wd2, Wu0, Wu1, Wu2);
    prep_didx<<<PB, 256>>>(nmsk, nidx);

    // conv chain
    conv_mma<8, 32, 0><<<NTILE, 128>>>(xb, wi + 0, nullptr, t1b);                   // conv1
    conv_mma<32, 8, 0><<<NTILE, 128>>>((const uint4*)t1b, wi + 1792, nullptr, sab); // conv2
    conv_mma<8,  8, 1><<<NTILE, 128>>>((const uint4*)sab, wi + 2688, x, sbb);       // conv3
    conv_mma<8,  8, 0><<<NTILE, 128>>>((const uint4*)sbb, wi + 3136, nullptr, sab); // conv4
    conv_mma<8, 32, 0><<<NTILE, 128>>>((const uint4*)sab, wi + 3584, nullptr, t5b); // conv5
    conv_mma<32, 32, 2><<<NTILE, 128>>>((const uint4*)t5b, wi + 5376, x, outp);     // conv6
    (void)in_sizes; (void)n_in; (void)out_size;
}